// round 9
// baseline (speedup 1.0000x reference)
#include <cuda_runtime.h>
#include <cuda_fp16.h>
#include <math.h>

// ---------------------------------------------------------------------------
// Instant-NGP multires hash-grid encoding, R9.
//
// L1tex serves ~1 scattered lane-access/cycle/SM (confirmed R8). Minimize
// scattered access count per thread:
//   levels 0-4:  dense pair tables (4 x 8B)                      [R6/R8]
//   levels 5-15: hash pair (fx, fx+1) differs by XOR mask 2^(t+1)-1
//                (t = trailing ones of fx). Redundant pair tables:
//       fx even        -> E natural pair      (1 x 8B)   50%
//       fx % 4 == 1    -> B1[h]=(v[h],v[h^3]) (1 x 8B)   25%
//       fx % 8 == 3    -> B2[h]=(v[h],v[h^7]) (1 x 8B)   12.5%
//       fx % 8 == 7    -> 2 x 4B fallback               12.5%
// Avg scattered accesses/thread: 5.375 -> 4.34 (-19%).
// ---------------------------------------------------------------------------

#define NUM_LEVELS 16
#define LOG2_T     19
#define T_CONST    (1u << LOG2_T)
#define T_MASK     (T_CONST - 1u)
#define TAB_ENTRIES (1u << 23)        // T * 16
#define N_DENSE_LEVELS 5
#define HASH_LEVELS 11
#define DENSE_TOTAL 533601            // 17^3+24^3+34^3+49^3+71^3

__device__ float    g_scale[NUM_LEVELS];
__device__ unsigned g_tab[TAB_ENTRIES];        // [0,4.27MB): dense pairs (uint2)
                                               // entries [5T,16T): half2 E shadow
__device__ uint2    g_b1[HASH_LEVELS << LOG2_T];  // (v[h], v[h^3]) 46MB
__device__ uint2    g_b2[HASH_LEVELS << LOG2_T];  // (v[h], v[h^7]) 46MB

__constant__ int c_denseR[N_DENSE_LEVELS]   = {17, 24, 34, 49, 71};
__constant__ int c_denseOff[N_DENSE_LEVELS] = {0, 4913, 18737, 58041, 175690};

// Replicate numpy's float64 scaling chain (verified matching R2/R5/R8).
__global__ void init_scales_kernel() {
    int l = threadIdx.x;
    if (l < NUM_LEVELS) {
        double growth = exp((log(4096.0) - log(16.0)) / 15.0);
        double s = floor(16.0 * pow(growth, (double)l));
        g_scale[l] = (float)s;
    }
}

// Fused prep for hash levels 5..15: convert f32 -> half2 E shadow AND build
// B1/B2 XOR-pair tables. One thread per 8-entry group.
__global__ __launch_bounds__(256) void build_shadow_kernel(const float4* __restrict__ src) {
    unsigned i = blockIdx.x * blockDim.x + threadIdx.x;   // < 11 * T/8
    unsigned lvl5 = i >> 16;                               // T/8 = 65536
    unsigned g    = i & 65535u;

    unsigned e0 = (lvl5 + 5u) * T_CONST + 8u * g;          // absolute entry
    const float4* s4 = src + (e0 >> 1);                    // 2 entries per float4

    unsigned v[8];
    #pragma unroll
    for (int j = 0; j < 4; j++) {
        float4 w = __ldg(s4 + j);
        __half2 a = __floats2half2_rn(w.x, w.y);
        __half2 b = __floats2half2_rn(w.z, w.w);
        v[2*j]   = *reinterpret_cast<unsigned*>(&a);
        v[2*j+1] = *reinterpret_cast<unsigned*>(&b);
    }

    // E shadow: 8 consecutive half2 entries = 32B
    uint4* ep = reinterpret_cast<uint4*>(g_tab + e0);
    ep[0] = make_uint4(v[0], v[1], v[2], v[3]);
    ep[1] = make_uint4(v[4], v[5], v[6], v[7]);

    // B1/B2: level-local base
    unsigned bb = lvl5 * T_CONST + 8u * g;
    #pragma unroll
    for (int j = 0; j < 8; j++) {
        g_b1[bb + j] = make_uint2(v[j], v[j ^ 3]);
        g_b2[bb + j] = make_uint2(v[j], v[j ^ 7]);
    }
}

// Dense pair tables for levels 0..4 in the dead front of g_tab (entries < 5T).
__global__ __launch_bounds__(256) void dense_fill_kernel(const float2* __restrict__ src) {
    int e = blockIdx.x * blockDim.x + threadIdx.x;
    if (e >= DENSE_TOTAL) return;

    int l = 0;
    #pragma unroll
    for (int i = 1; i < N_DENSE_LEVELS; i++)
        if (e >= c_denseOff[i]) l = i;

    int r = e - c_denseOff[l];
    int R = c_denseR[l];
    int z = r / (R * R);
    int rem = r - z * R * R;
    int y = rem / R;
    int x = rem - y * R;

    unsigned h = ((unsigned)x ^ ((unsigned)y * 2654435761u) ^ ((unsigned)z * 805459861u)) & T_MASK;
    h += (unsigned)l << LOG2_T;

    float2 fv = __ldg(src + h);
    __half2 hv = __floats2half2_rn(fv.x, fv.y);
    unsigned v = *reinterpret_cast<unsigned*>(&hv);

    g_tab[2 * e] = v;                 // pair[e].x  (floor-x corner)
    if (x > 0) g_tab[2 * e - 1] = v;  // pair[e-1].y (ceil-x corner of prev)
}

__device__ __forceinline__ float2 h2f(unsigned bits) {
    __half2 h = *reinterpret_cast<__half2*>(&bits);
    return __half22float2(h);
}

__global__ __launch_bounds__(256) void hashgrid_kernel(
    const float*  __restrict__ pts,   // [npts, 3]
    float2*       __restrict__ out,   // [npts, 16] float2
    int npts)
{
    int t = blockIdx.x * blockDim.x + threadIdx.x;
    int p = t >> 4;
    int l = t & (NUM_LEVELS - 1);
    if (p >= npts) return;

    float x = __ldg(pts + 3 * p + 0);
    float y = __ldg(pts + 3 * p + 1);
    float z = __ldg(pts + 3 * p + 2);

    float s = g_scale[l];
    float sx = x * s, sy = y * s, sz = z * s;

    float fxf = floorf(sx), fyf = floorf(sy), fzf = floorf(sz);
    float ox = sx - fxf, oy = sy - fyf, oz = sz - fzf;

    int fx = (int)fxf,       fy = (int)fyf,       fz = (int)fzf;
    int cx = (int)ceilf(sx), cy = (int)ceilf(sy), cz = (int)ceilf(sz);

    // Corner values (half2 bits). v f/c = floor-x / ceil-x corner.
    unsigned vf03, vc03, vf12, vc12, vf56, vc56, vf47, vc47;

    if (l < N_DENSE_LEVELS) {
        // ---- dense path: 4 aligned 8B loads ----
        int R  = c_denseR[l];
        int R2 = R * R;
        int off = c_denseOff[l];

        int j03 = off + fx + cy * R + cz * R2;
        int j12 = off + fx + fy * R + cz * R2;
        int j56 = off + fx + fy * R + fz * R2;
        int j47 = off + fx + cy * R + fz * R2;

        const uint2* dp = reinterpret_cast<const uint2*>(g_tab);
        uint2 P03 = __ldg(dp + j03);
        uint2 P12 = __ldg(dp + j12);
        uint2 P56 = __ldg(dp + j56);
        uint2 P47 = __ldg(dp + j47);

        vf03 = P03.x; vc03 = P03.y;
        vf12 = P12.x; vc12 = P12.y;
        vf56 = P56.x; vc56 = P56.y;
        vf47 = P47.x; vc47 = P47.y;
        // Exact-integer sx: "ceil" slot wrong value but weight ox == 0.
    } else {
        // ---- hash path: per-pair y/z hash parts ----
        unsigned hcy = (unsigned)cy * 2654435761u;
        unsigned hfy = (unsigned)fy * 2654435761u;
        unsigned hcz = (unsigned)cz * 805459861u;
        unsigned hfz = (unsigned)fz * 805459861u;

        unsigned r03 = hcy ^ hcz;
        unsigned r12 = hfy ^ hcz;
        unsigned r56 = hfy ^ hfz;
        unsigned r47 = hcy ^ hfz;

        unsigned ufx = (unsigned)fx;
        unsigned loc03 = (ufx ^ r03) & T_MASK;   // level-local floor indices
        unsigned loc12 = (ufx ^ r12) & T_MASK;
        unsigned loc56 = (ufx ^ r56) & T_MASK;
        unsigned loc47 = (ufx ^ r47) & T_MASK;

        unsigned lbase = (unsigned)l << LOG2_T;          // E (absolute)
        unsigned bbase = (unsigned)(l - 5) << LOG2_T;    // B1/B2 (level-local)

        int cls = fx & 7;
        if (!(fx & 1)) {
            // fx even: natural adjacent pair in E (ceil = floor^1)
            const uint2* gp = reinterpret_cast<const uint2*>(g_tab);
            uint2 P03 = __ldg(gp + ((lbase + loc03) >> 1));
            uint2 P12 = __ldg(gp + ((lbase + loc12) >> 1));
            uint2 P56 = __ldg(gp + ((lbase + loc56) >> 1));
            uint2 P47 = __ldg(gp + ((lbase + loc47) >> 1));
            bool h03 = loc03 & 1u, h12 = loc12 & 1u, h56 = loc56 & 1u, h47 = loc47 & 1u;
            vf03 = h03 ? P03.y : P03.x;  vc03 = h03 ? P03.x : P03.y;
            vf12 = h12 ? P12.y : P12.x;  vc12 = h12 ? P12.x : P12.y;
            vf56 = h56 ? P56.y : P56.x;  vc56 = h56 ? P56.x : P56.y;
            vf47 = h47 ? P47.y : P47.x;  vc47 = h47 ? P47.x : P47.y;
        } else if ((cls & 3) == 1) {
            // fx % 4 == 1: ceil index = floor ^ 3
            uint2 Q03 = __ldg(g_b1 + bbase + loc03);
            uint2 Q12 = __ldg(g_b1 + bbase + loc12);
            uint2 Q56 = __ldg(g_b1 + bbase + loc56);
            uint2 Q47 = __ldg(g_b1 + bbase + loc47);
            vf03 = Q03.x; vc03 = Q03.y;
            vf12 = Q12.x; vc12 = Q12.y;
            vf56 = Q56.x; vc56 = Q56.y;
            vf47 = Q47.x; vc47 = Q47.y;
        } else if (cls == 3) {
            // fx % 8 == 3: ceil index = floor ^ 7
            uint2 Q03 = __ldg(g_b2 + bbase + loc03);
            uint2 Q12 = __ldg(g_b2 + bbase + loc12);
            uint2 Q56 = __ldg(g_b2 + bbase + loc56);
            uint2 Q47 = __ldg(g_b2 + bbase + loc47);
            vf03 = Q03.x; vc03 = Q03.y;
            vf12 = Q12.x; vc12 = Q12.y;
            vf56 = Q56.x; vc56 = Q56.y;
            vf47 = Q47.x; vc47 = Q47.y;
        } else {
            // fx % 8 == 7: fallback, two 4B loads per pair
            unsigned ucx = (unsigned)cx;
            vf03 = __ldg(g_tab + lbase + loc03);
            vf12 = __ldg(g_tab + lbase + loc12);
            vf56 = __ldg(g_tab + lbase + loc56);
            vf47 = __ldg(g_tab + lbase + loc47);
            vc03 = __ldg(g_tab + lbase + ((ucx ^ r03) & T_MASK));
            vc12 = __ldg(g_tab + lbase + ((ucx ^ r12) & T_MASK));
            vc56 = __ldg(g_tab + lbase + ((ucx ^ r56) & T_MASK));
            vc47 = __ldg(g_tab + lbase + ((ucx ^ r47) & T_MASK));
        }
        // All B paths: exact-integer sx gives wrong ceil value, weight 0.
    }

    float2 f0 = h2f(vc03), f3 = h2f(vf03);
    float2 f1 = h2f(vc12), f2 = h2f(vf12);
    float2 f5 = h2f(vc56), f6 = h2f(vf56);
    float2 f4 = h2f(vc47), f7 = h2f(vf47);

    float mx = 1.0f - ox, my = 1.0f - oy, mz = 1.0f - oz;

    // x-lerp (ceil-x corner weighted by ox, per reference)
    float a03x = f0.x * ox + f3.x * mx;
    float a03y = f0.y * ox + f3.y * mx;
    float a12x = f1.x * ox + f2.x * mx;
    float a12y = f1.y * ox + f2.y * mx;
    float a56x = f5.x * ox + f6.x * mx;
    float a56y = f5.y * ox + f6.y * mx;
    float a47x = f4.x * ox + f7.x * mx;
    float a47y = f4.y * ox + f7.y * mx;

    // y-lerp
    float bx = a03x * oy + a12x * my;
    float by = a03y * oy + a12y * my;
    float gx = a47x * oy + a56x * my;
    float gy = a47y * oy + a56y * my;

    // z-lerp
    float2 e;
    e.x = bx * oz + gx * mz;
    e.y = by * oz + gy * mz;

    out[(size_t)p * NUM_LEVELS + l] = e;
}

extern "C" void kernel_launch(void* const* d_in, const int* in_sizes, int n_in,
                              void* d_out, int out_size) {
    const float* pts = (const float*)d_in[0];
    const float* tab = (const float*)d_in[1];
    float2*      out = (float2*)d_out;

    int npts = in_sizes[0] / 3;

    init_scales_kernel<<<1, 32>>>();

    // Hash levels 5..15: E shadow + B1/B2 pair tables (one thread / 8 entries).
    unsigned groups = HASH_LEVELS * (T_CONST / 8u);
    build_shadow_kernel<<<groups / 256, 256>>>((const float4*)tab);

    // Dense pair tables for levels 0..4 (front of g_tab).
    dense_fill_kernel<<<(DENSE_TOTAL + 255) / 256, 256>>>((const float2*)tab);

    long long total = (long long)npts * NUM_LEVELS;
    int threads = 256;
    int blocks = (int)((total + threads - 1) / threads);
    hashgrid_kernel<<<blocks, threads>>>(pts, out, npts);
}

// round 12
// speedup vs baseline: 1.1833x; 1.1833x over previous
#include <cuda_runtime.h>
#include <cuda_fp16.h>
#include <math.h>

// ---------------------------------------------------------------------------
// Instant-NGP multires hash-grid encoding, R12 (= R10 algorithm, statics
// merged into ONE __device__ array after R10's bytes failed twice on the
// recurring broker error — same restructure protocol that cleared R6/R7).
//
// Wavefront model (validated R8 within 3%): time ~ scattered lane-accesses
// through L1tex, PROVIDED tables stay L2-resident (R9's 124MB blew L2).
//   levels 0-4:  dense pair tables            4 x 8B
//   levels 5-15: fx even      -> E pair       4 x 8B      (50%)
//                fx % 4 == 1  -> B1 pair      4 x 8B      (25%)
//                fx % 4 == 3  -> pair+extras  4x8B + 4x4B (25%)
// Avg accesses/thread: 5.375 -> 4.69 (-13%).
// Layout of g_mem (unsigned entries):
//   [0, 2*DENSE_TOTAL)        dense pairs (uint2 aliased), levels 0-4
//   [5T, 16T)                 half2 E shadow, levels 5-15
//   [16T, 16T + 2*11T)        B1[h] = (v[h], v[h^3]) (uint2), levels 5-15
// ---------------------------------------------------------------------------

#define NUM_LEVELS 16
#define LOG2_T     19
#define T_CONST    (1u << LOG2_T)
#define T_MASK     (T_CONST - 1u)
#define TAB_ENTRIES (1u << 23)        // 16*T unsigned
#define N_DENSE_LEVELS 5
#define HASH_LEVELS 11
#define DENSE_TOTAL 533601            // 17^3+24^3+34^3+49^3+71^3
#define B1_BASE TAB_ENTRIES           // unsigned offset of B1 region

__device__ float    g_scale[NUM_LEVELS];
__device__ unsigned g_mem[TAB_ENTRIES + 2u * (HASH_LEVELS << LOG2_T)];  // 80MB

__constant__ int c_denseR[N_DENSE_LEVELS]   = {17, 24, 34, 49, 71};
__constant__ int c_denseOff[N_DENSE_LEVELS] = {0, 4913, 18737, 58041, 175690};

// Replicate numpy's float64 scaling chain (verified matching R2/R5/R8).
__global__ void init_scales_kernel() {
    int l = threadIdx.x;
    if (l < NUM_LEVELS) {
        double growth = exp((log(4096.0) - log(16.0)) / 15.0);
        double s = floor(16.0 * pow(growth, (double)l));
        g_scale[l] = (float)s;
    }
}

// Fused prep for hash levels 5..15: f32 -> half2 E shadow AND B1 pair table.
// One thread per 4-entry group (h^3 stays inside the group).
__global__ __launch_bounds__(256) void build_shadow_kernel(const float4* __restrict__ src) {
    unsigned i = blockIdx.x * blockDim.x + threadIdx.x;   // < 11 * T/4
    unsigned lvl5 = i >> 17;                               // T/4 = 131072
    unsigned g    = i & 131071u;

    unsigned e0 = (lvl5 + 5u) * T_CONST + 4u * g;          // absolute entry
    const float4* s4 = src + (e0 >> 1);

    unsigned v[4];
    #pragma unroll
    for (int j = 0; j < 2; j++) {
        float4 w = __ldg(s4 + j);
        __half2 a = __floats2half2_rn(w.x, w.y);
        __half2 b = __floats2half2_rn(w.z, w.w);
        v[2*j]   = *reinterpret_cast<unsigned*>(&a);
        v[2*j+1] = *reinterpret_cast<unsigned*>(&b);
    }

    // E shadow: 4 consecutive half2 entries = 16B
    *reinterpret_cast<uint4*>(g_mem + e0) = make_uint4(v[0], v[1], v[2], v[3]);

    // B1 (level-local): B1[h] = (v[h], v[h^3])
    uint2* b1 = reinterpret_cast<uint2*>(g_mem + B1_BASE);
    unsigned bb = lvl5 * T_CONST + 4u * g;
    #pragma unroll
    for (int j = 0; j < 4; j++)
        b1[bb + j] = make_uint2(v[j], v[j ^ 3]);
}

// Dense pair tables for levels 0..4 in the dead front of g_mem (entries < 5T).
__global__ __launch_bounds__(256) void dense_fill_kernel(const float2* __restrict__ src) {
    int e = blockIdx.x * blockDim.x + threadIdx.x;
    if (e >= DENSE_TOTAL) return;

    int l = 0;
    #pragma unroll
    for (int i = 1; i < N_DENSE_LEVELS; i++)
        if (e >= c_denseOff[i]) l = i;

    int r = e - c_denseOff[l];
    int R = c_denseR[l];
    int z = r / (R * R);
    int rem = r - z * R * R;
    int y = rem / R;
    int x = rem - y * R;

    unsigned h = ((unsigned)x ^ ((unsigned)y * 2654435761u) ^ ((unsigned)z * 805459861u)) & T_MASK;
    h += (unsigned)l << LOG2_T;

    float2 fv = __ldg(src + h);
    __half2 hv = __floats2half2_rn(fv.x, fv.y);
    unsigned v = *reinterpret_cast<unsigned*>(&hv);

    g_mem[2 * e] = v;                 // pair[e].x  (floor-x corner)
    if (x > 0) g_mem[2 * e - 1] = v;  // pair[e-1].y (ceil-x corner of prev)
}

__device__ __forceinline__ float2 h2f(unsigned bits) {
    __half2 h = *reinterpret_cast<__half2*>(&bits);
    return __half22float2(h);
}

__global__ __launch_bounds__(256) void hashgrid_kernel(
    const float*  __restrict__ pts,   // [npts, 3]
    float2*       __restrict__ out,   // [npts, 16] float2
    int npts)
{
    int t = blockIdx.x * blockDim.x + threadIdx.x;
    int p = t >> 4;
    int l = t & (NUM_LEVELS - 1);
    if (p >= npts) return;

    float x = __ldg(pts + 3 * p + 0);
    float y = __ldg(pts + 3 * p + 1);
    float z = __ldg(pts + 3 * p + 2);

    float s = g_scale[l];
    float sx = x * s, sy = y * s, sz = z * s;

    float fxf = floorf(sx), fyf = floorf(sy), fzf = floorf(sz);
    float ox = sx - fxf, oy = sy - fyf, oz = sz - fzf;

    int fx = (int)fxf,       fy = (int)fyf,       fz = (int)fzf;
    int cx = (int)ceilf(sx), cy = (int)ceilf(sy), cz = (int)ceilf(sz);

    // Corner values (half2 bits). vf*/vc* = floor-x / ceil-x corner.
    unsigned vf03, vc03, vf12, vc12, vf56, vc56, vf47, vc47;

    if (l < N_DENSE_LEVELS) {
        // ---- dense path: 4 aligned 8B loads ----
        int R  = c_denseR[l];
        int R2 = R * R;
        int off = c_denseOff[l];

        int j03 = off + fx + cy * R + cz * R2;
        int j12 = off + fx + fy * R + cz * R2;
        int j56 = off + fx + fy * R + fz * R2;
        int j47 = off + fx + cy * R + fz * R2;

        const uint2* dp = reinterpret_cast<const uint2*>(g_mem);
        uint2 P03 = __ldg(dp + j03);
        uint2 P12 = __ldg(dp + j12);
        uint2 P56 = __ldg(dp + j56);
        uint2 P47 = __ldg(dp + j47);

        vf03 = P03.x; vc03 = P03.y;
        vf12 = P12.x; vc12 = P12.y;
        vf56 = P56.x; vc56 = P56.y;
        vf47 = P47.x; vc47 = P47.y;
        // Exact-integer sx: "ceil" slot wrong value but weight ox == 0.
    } else {
        // ---- hash path ----
        unsigned hcy = (unsigned)cy * 2654435761u;
        unsigned hfy = (unsigned)fy * 2654435761u;
        unsigned hcz = (unsigned)cz * 805459861u;
        unsigned hfz = (unsigned)fz * 805459861u;

        unsigned r03 = hcy ^ hcz;
        unsigned r12 = hfy ^ hcz;
        unsigned r56 = hfy ^ hfz;
        unsigned r47 = hcy ^ hfz;

        unsigned ufx = (unsigned)fx;
        unsigned loc03 = (ufx ^ r03) & T_MASK;   // level-local floor indices
        unsigned loc12 = (ufx ^ r12) & T_MASK;
        unsigned loc56 = (ufx ^ r56) & T_MASK;
        unsigned loc47 = (ufx ^ r47) & T_MASK;

        unsigned lbase = (unsigned)l << LOG2_T;          // E (absolute)

        if (!(fx & 1)) {
            // fx even: ceil = floor^1, natural adjacent pair in E.
            const uint2* gp = reinterpret_cast<const uint2*>(g_mem);
            uint2 P03 = __ldg(gp + ((lbase + loc03) >> 1));
            uint2 P12 = __ldg(gp + ((lbase + loc12) >> 1));
            uint2 P56 = __ldg(gp + ((lbase + loc56) >> 1));
            uint2 P47 = __ldg(gp + ((lbase + loc47) >> 1));
            bool h03 = loc03 & 1u, h12 = loc12 & 1u, h56 = loc56 & 1u, h47 = loc47 & 1u;
            vf03 = h03 ? P03.y : P03.x;  vc03 = h03 ? P03.x : P03.y;
            vf12 = h12 ? P12.y : P12.x;  vc12 = h12 ? P12.x : P12.y;
            vf56 = h56 ? P56.y : P56.x;  vc56 = h56 ? P56.x : P56.y;
            vf47 = h47 ? P47.y : P47.x;  vc47 = h47 ? P47.x : P47.y;
        } else if ((fx & 3) == 1) {
            // fx % 4 == 1: ceil index = floor ^ 3 -> B1 pair, 1 x 8B each.
            const uint2* b1 = reinterpret_cast<const uint2*>(g_mem + B1_BASE);
            unsigned bbase = (unsigned)(l - 5) << LOG2_T;
            uint2 Q03 = __ldg(b1 + bbase + loc03);
            uint2 Q12 = __ldg(b1 + bbase + loc12);
            uint2 Q56 = __ldg(b1 + bbase + loc56);
            uint2 Q47 = __ldg(b1 + bbase + loc47);
            vf03 = Q03.x; vc03 = Q03.y;
            vf12 = Q12.x; vc12 = Q12.y;
            vf56 = Q56.x; vc56 = Q56.y;
            vf47 = Q47.x; vc47 = Q47.y;
        } else {
            // fx % 4 == 3: E pair (floor) + 4B extras (ceil).
            const uint2* gp = reinterpret_cast<const uint2*>(g_mem);
            uint2 P03 = __ldg(gp + ((lbase + loc03) >> 1));
            uint2 P12 = __ldg(gp + ((lbase + loc12) >> 1));
            uint2 P56 = __ldg(gp + ((lbase + loc56) >> 1));
            uint2 P47 = __ldg(gp + ((lbase + loc47) >> 1));
            unsigned ucx = (unsigned)cx;
            vc03 = __ldg(g_mem + lbase + ((ucx ^ r03) & T_MASK));
            vc12 = __ldg(g_mem + lbase + ((ucx ^ r12) & T_MASK));
            vc56 = __ldg(g_mem + lbase + ((ucx ^ r56) & T_MASK));
            vc47 = __ldg(g_mem + lbase + ((ucx ^ r47) & T_MASK));
            vf03 = (loc03 & 1u) ? P03.y : P03.x;
            vf12 = (loc12 & 1u) ? P12.y : P12.x;
            vf56 = (loc56 & 1u) ? P56.y : P56.x;
            vf47 = (loc47 & 1u) ? P47.y : P47.x;
        }
        // Exact-integer sx (cx==fx) in even/B1 paths: wrong ceil value,
        // but its weight ox is exactly 0, so the result is exact.
    }

    float2 f0 = h2f(vc03), f3 = h2f(vf03);
    float2 f1 = h2f(vc12), f2 = h2f(vf12);
    float2 f5 = h2f(vc56), f6 = h2f(vf56);
    float2 f4 = h2f(vc47), f7 = h2f(vf47);

    float mx = 1.0f - ox, my = 1.0f - oy, mz = 1.0f - oz;

    // x-lerp (ceil-x corner weighted by ox, per reference)
    float a03x = f0.x * ox + f3.x * mx;
    float a03y = f0.y * ox + f3.y * mx;
    float a12x = f1.x * ox + f2.x * mx;
    float a12y = f1.y * ox + f2.y * mx;
    float a56x = f5.x * ox + f6.x * mx;
    float a56y = f5.y * ox + f6.y * mx;
    float a47x = f4.x * ox + f7.x * mx;
    float a47y = f4.y * ox + f7.y * mx;

    // y-lerp
    float bx = a03x * oy + a12x * my;
    float by = a03y * oy + a12y * my;
    float gx = a47x * oy + a56x * my;
    float gy = a47y * oy + a56y * my;

    // z-lerp
    float2 e;
    e.x = bx * oz + gx * mz;
    e.y = by * oz + gy * mz;

    out[(size_t)p * NUM_LEVELS + l] = e;
}

extern "C" void kernel_launch(void* const* d_in, const int* in_sizes, int n_in,
                              void* d_out, int out_size) {
    const float* pts = (const float*)d_in[0];
    const float* tab = (const float*)d_in[1];
    float2*      out = (float2*)d_out;

    int npts = in_sizes[0] / 3;

    init_scales_kernel<<<1, 32>>>();

    // Hash levels 5..15: E shadow + B1 pair table (one thread / 4 entries).
    unsigned groups = HASH_LEVELS * (T_CONST / 4u);
    build_shadow_kernel<<<groups / 256, 256>>>((const float4*)tab);

    // Dense pair tables for levels 0..4 (front of g_mem).
    dense_fill_kernel<<<(DENSE_TOTAL + 255) / 256, 256>>>((const float2*)tab);

    long long total = (long long)npts * NUM_LEVELS;
    int threads = 256;
    int blocks = (int)((total + threads - 1) / threads);
    hashgrid_kernel<<<blocks, threads>>>(pts, out, npts);
}

// round 14
// speedup vs baseline: 1.1847x; 1.0012x over previous
#include <cuda_runtime.h>
#include <cuda_fp16.h>
#include <math.h>

// ---------------------------------------------------------------------------
// Instant-NGP multires hash-grid encoding, R14.
//   = R13 with the level-15 scaling corrected: numpy's float64 chain gives
//   floor(4095.9999...) = 4095 (PROVEN by R13's rel_err=0.2899 signature with
//   4096 vs R2-R12 passing with the device-double replica).
//
//   1. __stcs streaming stores for the 128MB output -> stop evicting the
//      72MB hot tables from L2 (R12 showed 21.3% DRAM read exposure).
//   2. SCALINGS hardcoded in __constant__ -> init kernel deleted.
//   3. __ldcs on read-once point loads.
//
// Access scheme (wavefront model validated R8/R12):
//   levels 0-4:  dense pair tables            4 x 8B
//   levels 5-15: fx even      -> E pair       4 x 8B      (50%)
//                fx % 4 == 1  -> B1 pair      4 x 8B      (25%)
//                fx % 4 == 3  -> pair+extras  4x8B + 4x4B (25%)
// ---------------------------------------------------------------------------

#define NUM_LEVELS 16
#define LOG2_T     19
#define T_CONST    (1u << LOG2_T)
#define T_MASK     (T_CONST - 1u)
#define TAB_ENTRIES (1u << 23)        // 16*T unsigned
#define N_DENSE_LEVELS 5
#define HASH_LEVELS 11
#define DENSE_TOTAL 533601            // 17^3+24^3+34^3+49^3+71^3
#define B1_BASE TAB_ENTRIES           // unsigned offset of B1 region

__device__ unsigned g_mem[TAB_ENTRIES + 2u * (HASH_LEVELS << LOG2_T)];  // 80MB

// floor(16 * growth^l) per numpy's float64 chain. Level 15 is 4095, NOT 4096:
// 16*growth^15 = 4095.9999... in f64 (proven empirically: 4096 -> rel_err 0.29
// in R13; the device-double replica used R2-R12 passed).
__constant__ float c_scale[NUM_LEVELS] = {
    16.f, 23.f, 33.f, 48.f, 70.f, 101.f, 147.f, 212.f,
    307.f, 445.f, 645.f, 933.f, 1351.f, 1955.f, 2830.f, 4095.f
};

__constant__ int c_denseR[N_DENSE_LEVELS]   = {17, 24, 34, 49, 71};
__constant__ int c_denseOff[N_DENSE_LEVELS] = {0, 4913, 18737, 58041, 175690};

// Fused prep for hash levels 5..15: f32 -> half2 E shadow AND B1 pair table.
// One thread per 4-entry group (h^3 stays inside the group).
__global__ __launch_bounds__(256) void build_shadow_kernel(const float4* __restrict__ src) {
    unsigned i = blockIdx.x * blockDim.x + threadIdx.x;   // < 11 * T/4
    unsigned lvl5 = i >> 17;                               // T/4 = 131072
    unsigned g    = i & 131071u;

    unsigned e0 = (lvl5 + 5u) * T_CONST + 4u * g;          // absolute entry
    const float4* s4 = src + (e0 >> 1);

    unsigned v[4];
    #pragma unroll
    for (int j = 0; j < 2; j++) {
        float4 w = __ldg(s4 + j);
        __half2 a = __floats2half2_rn(w.x, w.y);
        __half2 b = __floats2half2_rn(w.z, w.w);
        v[2*j]   = *reinterpret_cast<unsigned*>(&a);
        v[2*j+1] = *reinterpret_cast<unsigned*>(&b);
    }

    // E shadow: 4 consecutive half2 entries = 16B
    *reinterpret_cast<uint4*>(g_mem + e0) = make_uint4(v[0], v[1], v[2], v[3]);

    // B1 (level-local): B1[h] = (v[h], v[h^3])
    uint2* b1 = reinterpret_cast<uint2*>(g_mem + B1_BASE);
    unsigned bb = lvl5 * T_CONST + 4u * g;
    #pragma unroll
    for (int j = 0; j < 4; j++)
        b1[bb + j] = make_uint2(v[j], v[j ^ 3]);
}

// Dense pair tables for levels 0..4 in the dead front of g_mem (entries < 5T).
__global__ __launch_bounds__(256) void dense_fill_kernel(const float2* __restrict__ src) {
    int e = blockIdx.x * blockDim.x + threadIdx.x;
    if (e >= DENSE_TOTAL) return;

    int l = 0;
    #pragma unroll
    for (int i = 1; i < N_DENSE_LEVELS; i++)
        if (e >= c_denseOff[i]) l = i;

    int r = e - c_denseOff[l];
    int R = c_denseR[l];
    int z = r / (R * R);
    int rem = r - z * R * R;
    int y = rem / R;
    int x = rem - y * R;

    unsigned h = ((unsigned)x ^ ((unsigned)y * 2654435761u) ^ ((unsigned)z * 805459861u)) & T_MASK;
    h += (unsigned)l << LOG2_T;

    float2 fv = __ldg(src + h);
    __half2 hv = __floats2half2_rn(fv.x, fv.y);
    unsigned v = *reinterpret_cast<unsigned*>(&hv);

    g_mem[2 * e] = v;                 // pair[e].x  (floor-x corner)
    if (x > 0) g_mem[2 * e - 1] = v;  // pair[e-1].y (ceil-x corner of prev)
}

__device__ __forceinline__ float2 h2f(unsigned bits) {
    __half2 h = *reinterpret_cast<__half2*>(&bits);
    return __half22float2(h);
}

__global__ __launch_bounds__(256) void hashgrid_kernel(
    const float*  __restrict__ pts,   // [npts, 3]
    float2*       __restrict__ out,   // [npts, 16] float2
    int npts)
{
    int t = blockIdx.x * blockDim.x + threadIdx.x;
    int p = t >> 4;
    int l = t & (NUM_LEVELS - 1);
    if (p >= npts) return;

    // Read-once point loads: streaming hint keeps them out of the hot L2 set.
    float x = __ldcs(pts + 3 * p + 0);
    float y = __ldcs(pts + 3 * p + 1);
    float z = __ldcs(pts + 3 * p + 2);

    float s = c_scale[l];
    float sx = x * s, sy = y * s, sz = z * s;

    float fxf = floorf(sx), fyf = floorf(sy), fzf = floorf(sz);
    float ox = sx - fxf, oy = sy - fyf, oz = sz - fzf;

    int fx = (int)fxf,       fy = (int)fyf,       fz = (int)fzf;
    int cx = (int)ceilf(sx), cy = (int)ceilf(sy), cz = (int)ceilf(sz);

    // Corner values (half2 bits). vf*/vc* = floor-x / ceil-x corner.
    unsigned vf03, vc03, vf12, vc12, vf56, vc56, vf47, vc47;

    if (l < N_DENSE_LEVELS) {
        // ---- dense path: 4 aligned 8B loads ----
        int R  = c_denseR[l];
        int R2 = R * R;
        int off = c_denseOff[l];

        int j03 = off + fx + cy * R + cz * R2;
        int j12 = off + fx + fy * R + cz * R2;
        int j56 = off + fx + fy * R + fz * R2;
        int j47 = off + fx + cy * R + fz * R2;

        const uint2* dp = reinterpret_cast<const uint2*>(g_mem);
        uint2 P03 = __ldg(dp + j03);
        uint2 P12 = __ldg(dp + j12);
        uint2 P56 = __ldg(dp + j56);
        uint2 P47 = __ldg(dp + j47);

        vf03 = P03.x; vc03 = P03.y;
        vf12 = P12.x; vc12 = P12.y;
        vf56 = P56.x; vc56 = P56.y;
        vf47 = P47.x; vc47 = P47.y;
        // Exact-integer sx: "ceil" slot wrong value but weight ox == 0.
    } else {
        // ---- hash path ----
        unsigned hcy = (unsigned)cy * 2654435761u;
        unsigned hfy = (unsigned)fy * 2654435761u;
        unsigned hcz = (unsigned)cz * 805459861u;
        unsigned hfz = (unsigned)fz * 805459861u;

        unsigned r03 = hcy ^ hcz;
        unsigned r12 = hfy ^ hcz;
        unsigned r56 = hfy ^ hfz;
        unsigned r47 = hcy ^ hfz;

        unsigned ufx = (unsigned)fx;
        unsigned loc03 = (ufx ^ r03) & T_MASK;   // level-local floor indices
        unsigned loc12 = (ufx ^ r12) & T_MASK;
        unsigned loc56 = (ufx ^ r56) & T_MASK;
        unsigned loc47 = (ufx ^ r47) & T_MASK;

        unsigned lbase = (unsigned)l << LOG2_T;          // E (absolute)

        if (!(fx & 1)) {
            // fx even: ceil = floor^1, natural adjacent pair in E.
            const uint2* gp = reinterpret_cast<const uint2*>(g_mem);
            uint2 P03 = __ldg(gp + ((lbase + loc03) >> 1));
            uint2 P12 = __ldg(gp + ((lbase + loc12) >> 1));
            uint2 P56 = __ldg(gp + ((lbase + loc56) >> 1));
            uint2 P47 = __ldg(gp + ((lbase + loc47) >> 1));
            bool h03 = loc03 & 1u, h12 = loc12 & 1u, h56 = loc56 & 1u, h47 = loc47 & 1u;
            vf03 = h03 ? P03.y : P03.x;  vc03 = h03 ? P03.x : P03.y;
            vf12 = h12 ? P12.y : P12.x;  vc12 = h12 ? P12.x : P12.y;
            vf56 = h56 ? P56.y : P56.x;  vc56 = h56 ? P56.x : P56.y;
            vf47 = h47 ? P47.y : P47.x;  vc47 = h47 ? P47.x : P47.y;
        } else if ((fx & 3) == 1) {
            // fx % 4 == 1: ceil index = floor ^ 3 -> B1 pair, 1 x 8B each.
            const uint2* b1 = reinterpret_cast<const uint2*>(g_mem + B1_BASE);
            unsigned bbase = (unsigned)(l - 5) << LOG2_T;
            uint2 Q03 = __ldg(b1 + bbase + loc03);
            uint2 Q12 = __ldg(b1 + bbase + loc12);
            uint2 Q56 = __ldg(b1 + bbase + loc56);
            uint2 Q47 = __ldg(b1 + bbase + loc47);
            vf03 = Q03.x; vc03 = Q03.y;
            vf12 = Q12.x; vc12 = Q12.y;
            vf56 = Q56.x; vc56 = Q56.y;
            vf47 = Q47.x; vc47 = Q47.y;
        } else {
            // fx % 4 == 3: E pair (floor) + 4B extras (ceil).
            const uint2* gp = reinterpret_cast<const uint2*>(g_mem);
            uint2 P03 = __ldg(gp + ((lbase + loc03) >> 1));
            uint2 P12 = __ldg(gp + ((lbase + loc12) >> 1));
            uint2 P56 = __ldg(gp + ((lbase + loc56) >> 1));
            uint2 P47 = __ldg(gp + ((lbase + loc47) >> 1));
            unsigned ucx = (unsigned)cx;
            vc03 = __ldg(g_mem + lbase + ((ucx ^ r03) & T_MASK));
            vc12 = __ldg(g_mem + lbase + ((ucx ^ r12) & T_MASK));
            vc56 = __ldg(g_mem + lbase + ((ucx ^ r56) & T_MASK));
            vc47 = __ldg(g_mem + lbase + ((ucx ^ r47) & T_MASK));
            vf03 = (loc03 & 1u) ? P03.y : P03.x;
            vf12 = (loc12 & 1u) ? P12.y : P12.x;
            vf56 = (loc56 & 1u) ? P56.y : P56.x;
            vf47 = (loc47 & 1u) ? P47.y : P47.x;
        }
        // Exact-integer sx (cx==fx) in even/B1 paths: wrong ceil value,
        // but its weight ox is exactly 0, so the result is exact.
    }

    float2 f0 = h2f(vc03), f3 = h2f(vf03);
    float2 f1 = h2f(vc12), f2 = h2f(vf12);
    float2 f5 = h2f(vc56), f6 = h2f(vf56);
    float2 f4 = h2f(vc47), f7 = h2f(vf47);

    float mx = 1.0f - ox, my = 1.0f - oy, mz = 1.0f - oz;

    // x-lerp (ceil-x corner weighted by ox, per reference)
    float a03x = f0.x * ox + f3.x * mx;
    float a03y = f0.y * ox + f3.y * mx;
    float a12x = f1.x * ox + f2.x * mx;
    float a12y = f1.y * ox + f2.y * mx;
    float a56x = f5.x * ox + f6.x * mx;
    float a56y = f5.y * ox + f6.y * mx;
    float a47x = f4.x * ox + f7.x * mx;
    float a47y = f4.y * ox + f7.y * mx;

    // y-lerp
    float bx = a03x * oy + a12x * my;
    float by = a03y * oy + a12y * my;
    float gx = a47x * oy + a56x * my;
    float gy = a47y * oy + a56y * my;

    // z-lerp
    float2 e;
    e.x = bx * oz + gx * mz;
    e.y = by * oz + gy * mz;

    // Streaming store: output is write-once, keep it from evicting tables.
    __stcs(&out[(size_t)p * NUM_LEVELS + l], e);
}

extern "C" void kernel_launch(void* const* d_in, const int* in_sizes, int n_in,
                              void* d_out, int out_size) {
    const float* pts = (const float*)d_in[0];
    const float* tab = (const float*)d_in[1];
    float2*      out = (float2*)d_out;

    int npts = in_sizes[0] / 3;

    // Hash levels 5..15: E shadow + B1 pair table (one thread / 4 entries).
    unsigned groups = HASH_LEVELS * (T_CONST / 4u);
    build_shadow_kernel<<<groups / 256, 256>>>((const float4*)tab);

    // Dense pair tables for levels 0..4 (front of g_mem).
    dense_fill_kernel<<<(DENSE_TOTAL + 255) / 256, 256>>>((const float2*)tab);

    long long total = (long long)npts * NUM_LEVELS;
    int threads = 256;
    int blocks = (int)((total + threads - 1) / threads);
    hashgrid_kernel<<<blocks, threads>>>(pts, out, npts);
}